// round 14
// baseline (speedup 1.0000x reference)
#include <cuda_runtime.h>
#include <cstdint>

// FPS: B=2, Npb=131072, stride=32 -> M=4096 samples, 4095 serial rounds.
// KEY CHANGE (R13): both independent batch chains run in EVERY CTA,
// interleaved, so each chain's publish-flight/detect/consume dead time is
// hidden under the other chain's compute and consume. 128 CTAs * 256 thr *
// 4 pts/thr PER BATCH (same total register state as before); single wave.
// Per-round batch argmax still computed BY THE L2 ATOMIC UNIT on one line
// per (parity,batch): red.max of key=(t<<49|dist<<17|tail17) + release-add
// of a counter ON THE SAME LINE (R12 showed cross-line release costs ~670
// cyc/round). warp0 polls the 4B counter only; consume = relaxed key load +
// pts[idx] coord fetch (R7 tail).

#define NBATCH 2
#define CPB    128    // CTAs, shared by BOTH batches
#define TPB    256
#define PPTB   4      // points per thread PER BATCH (CPB*TPB*PPTB = 131072)
#define NPB    131072
#define MSAMP  4096
#define NW     (TPB / 32)
#define FLTMAX 3.402823466e38f

typedef unsigned long long u64;

struct __align__(16) Line { u64 key; unsigned cnt; unsigned _p; u64 _pad[14]; };
__device__ Line g_line[2][NBATCH];   // [round parity][batch], 128B apart

__global__ void reset_kernel() {
    int i = threadIdx.x;
    if (i < 2 * NBATCH) {
        g_line[i >> 1][i & 1].key = 0ULL;
        g_line[i >> 1][i & 1].cnt = 0u;
    }
}

__device__ __forceinline__ u64 f2pack(float lo, float hi) {
    u64 r; asm("mov.b64 %0, {%1,%2};" : "=l"(r) : "f"(lo), "f"(hi)); return r;
}
__device__ __forceinline__ void f2unpack(float& lo, float& hi, u64 v) {
    asm("mov.b64 {%0,%1}, %2;" : "=f"(lo), "=f"(hi) : "l"(v));
}
__device__ __forceinline__ u64 addx2(u64 a, u64 b) {   // per-lane IEEE rn add
    u64 r; asm("add.rn.f32x2 %0, %1, %2;" : "=l"(r) : "l"(a), "l"(b)); return r;
}
__device__ __forceinline__ u64 mulx2(u64 a, u64 b) {   // per-lane IEEE rn mul
    u64 r; asm("mul.rn.f32x2 %0, %1, %2;" : "=l"(r) : "l"(a), "l"(b)); return r;
}
__device__ __forceinline__ void red_max_u64(u64* p, u64 v) {
    asm volatile("red.relaxed.gpu.global.max.u64 [%0], %1;" :: "l"(p), "l"(v));
}
__device__ __forceinline__ void red_add_rel(unsigned* p, unsigned v) {
    asm volatile("red.release.gpu.global.add.u32 [%0], %1;" :: "l"(p), "r"(v));
}
__device__ __forceinline__ unsigned ld_acq_u32(const unsigned* p) {
    unsigned v;
    asm volatile("ld.acquire.gpu.global.u32 %0, [%1];" : "=r"(v) : "l"(p));
    return v;
}
__device__ __forceinline__ u64 ld_rlx_u64(const u64* p) {
    u64 v;
    asm volatile("ld.relaxed.gpu.global.u64 %0, [%1];" : "=l"(v) : "l"(p));
    return v;
}

// Local distance update + per-thread argmax + warp argmax for one batch's
// register-resident points. Exactness: unfused left-to-right
// (dx*dx + dy*dy) + dz*dz via per-lane rn f32x2 ops; bit compare == float
// compare for non-negative f32; strict > keeps lowest idx (idx ascends
// within the thread; tie across lanes broken by max tail = lowest idx).
__device__ __forceinline__ void local_round(
    const u64 (&x2)[PPTB / 2], const u64 (&y2)[PPTB / 2],
    const u64 (&z2)[PPTB / 2], float (&dist)[PPTB],
    const unsigned (&tail)[PPTB],
    float sx, float sy, float sz, unsigned& m_out, unsigned& mt_out)
{
    u64 nsx = f2pack(-sx, -sx);            // exact; x + (-s) == x - s in rn
    u64 nsy = f2pack(-sy, -sy);
    u64 nsz = f2pack(-sz, -sz);
    unsigned bdb = 0u, btl = 0u;
#pragma unroll
    for (int i = 0; i < PPTB / 2; ++i) {
        u64 dx = addx2(x2[i], nsx);
        u64 dy = addx2(y2[i], nsy);
        u64 dz = addx2(z2[i], nsz);
        u64 s  = addx2(addx2(mulx2(dx, dx), mulx2(dy, dy)), mulx2(dz, dz));
        float d0, d1; f2unpack(d0, d1, s);
        float nd0 = fminf(dist[2 * i], d0);
        float nd1 = fminf(dist[2 * i + 1], d1);
        dist[2 * i] = nd0; dist[2 * i + 1] = nd1;
        unsigned db0 = __float_as_uint(nd0);
        unsigned db1 = __float_as_uint(nd1);
        if (db0 > bdb) { bdb = db0; btl = tail[2 * i]; }
        if (db1 > bdb) { bdb = db1; btl = tail[2 * i + 1]; }
    }
    unsigned m  = __reduce_max_sync(0xFFFFFFFFu, bdb);
    unsigned mt = __reduce_max_sync(0xFFFFFFFFu, (bdb == m) ? btl : 0u);
    m_out = m; mt_out = mt;
}

__global__ void __launch_bounds__(TPB, 1)
fps_kernel(const float4* __restrict__ pts, float* __restrict__ out)
{
    const int c    = blockIdx.x;          // 0..127, chunk for BOTH batches
    const int tid  = threadIdx.x;
    const int lane = tid & 31;
    const int wid  = tid >> 5;

    const int lbase = c * (TPB * PPTB);   // in-batch base index of this chunk
    const float4* __restrict__ p1 = pts + NPB;   // batch-1 points

    // Register-resident state for BOTH batches (same total as before).
    u64 x0[PPTB / 2], y0[PPTB / 2], z0[PPTB / 2];
    u64 x1[PPTB / 2], y1[PPTB / 2], z1[PPTB / 2];
    float d0a[PPTB], d1a[PPTB];
    unsigned tl[PPTB];                    // shared tail: same local indices
#pragma unroll
    for (int i = 0; i < PPTB / 2; ++i) {
        int i0 = lbase + (2 * i) * TPB + tid;
        int i1 = lbase + (2 * i + 1) * TPB + tid;
        float4 a0 = pts[i0], a1 = pts[i1];
        float4 b0 = p1[i0],  b1 = p1[i1];
        x0[i] = f2pack(a0.y, a1.y); y0[i] = f2pack(a0.z, a1.z);
        z0[i] = f2pack(a0.w, a1.w);
        x1[i] = f2pack(b0.y, b1.y); y1[i] = f2pack(b0.z, b1.z);
        z1[i] = f2pack(b0.w, b1.w);
        d0a[2 * i] = FLTMAX; d0a[2 * i + 1] = FLTMAX;
        d1a[2 * i] = FLTMAX; d1a[2 * i + 1] = FLTMAX;
        tl[2 * i]     = 0x1FFFFu - (unsigned)i0;
        tl[2 * i + 1] = 0x1FFFFu - (unsigned)i1;
    }

    // Seeds = point 0 of each batch (pointops convention)
    float4 q0 = pts[0], q1 = p1[0];
    float s0x = q0.y, s0y = q0.z, s0z = q0.w;
    float s1x = q1.y, s1y = q1.z, s1z = q1.w;
    if (c == 0 && tid == 0) {
        ((float4*)out)[0]             = q0;
        ((float4*)out)[(size_t)MSAMP] = q1;
    }

    __shared__ unsigned s_db0[NW], s_tl0[NW], s_db1[NW], s_tl1[NW];
    __shared__ float    s_new[6];   // {x0,y0,z0, x1,y1,z1}

    for (int t = 1; t < MSAMP; ++t) {
        const unsigned target = (unsigned)CPB * (unsigned)((t + 1) >> 1);
        Line* L0 = &g_line[t & 1][0];
        Line* L1 = &g_line[t & 1][1];

        // ---- batch 0: local compute + warp argmax ----
        unsigned m0, mt0;
        local_round(x0, y0, z0, d0a, tl, s0x, s0y, s0z, m0, mt0);
        if (lane == 0) { s_db0[wid] = m0; s_tl0[wid] = mt0; }
        __syncthreads();                       // bar A

        // warp0 publishes b0 NOW -- its flight overlaps everyone's b1 compute
        if (wid == 0) {
            unsigned db = (lane < NW) ? s_db0[lane] : 0u;
            unsigned tv = (lane < NW) ? s_tl0[lane] : 0u;
            unsigned mm = __reduce_max_sync(0xFFFFFFFFu, db);
            unsigned mk = __reduce_max_sync(0xFFFFFFFFu, (db == mm) ? tv : 0u);
            if (lane == 0) {
                u64 key = ((u64)(unsigned)t << 49) | ((u64)mm << 17) | (u64)mk;
                red_max_u64(&L0->key, key);
                red_add_rel(&L0->cnt, 1u);     // same line: cheap release
            }
        }

        // ---- batch 1: local compute + warp argmax (covers b0 flight) ----
        unsigned m1, mt1;
        local_round(x1, y1, z1, d1a, tl, s1x, s1y, s1z, m1, mt1);
        if (lane == 0) { s_db1[wid] = m1; s_tl1[wid] = mt1; }
        __syncthreads();                       // bar B

        if (wid == 0) {
            // publish b1
            unsigned db = (lane < NW) ? s_db1[lane] : 0u;
            unsigned tv = (lane < NW) ? s_tl1[lane] : 0u;
            unsigned mm = __reduce_max_sync(0xFFFFFFFFu, db);
            unsigned mk = __reduce_max_sync(0xFFFFFFFFu, (db == mm) ? tv : 0u);
            if (lane == 0) {
                u64 key = ((u64)(unsigned)t << 49) | ((u64)mm << 17) | (u64)mk;
                red_max_u64(&L1->key, key);
                red_add_rel(&L1->cnt, 1u);
            }

            // ---- detect + consume b0 (flight mostly covered by b1 phase).
            // '>=' safe: parity line passes target only after every CTA
            // consumed round t (t+2 publish requires barC@t+1 > consume@t).
            while (ld_acq_u32(&L0->cnt) < target) { }
            u64 k0 = ld_rlx_u64(&L0->key);     // ordered after acquire
            float4 w0 = pts[0x1FFFFu - (unsigned)(k0 & 0x1FFFFu)];

            // ---- detect + consume b1 (overlaps w0's coord flight) ----
            while (ld_acq_u32(&L1->cnt) < target) { }
            u64 k1 = ld_rlx_u64(&L1->key);
            float4 w1 = p1[0x1FFFFu - (unsigned)(k1 & 0x1FFFFu)];

            if (lane == 0) {
                s_new[0] = w0.y; s_new[1] = w0.z; s_new[2] = w0.w;
                s_new[3] = w1.y; s_new[4] = w1.z; s_new[5] = w1.w;
                if (c == 0) {
                    ((float4*)out)[(size_t)t]         = w0;   // {0,x,y,z}
                    ((float4*)out)[(size_t)MSAMP + t] = w1;   // {1,x,y,z}
                }
            }
        }
        __syncthreads();                       // bar C
        s0x = s_new[0]; s0y = s_new[1]; s0z = s_new[2];
        s1x = s_new[3]; s1y = s_new[4]; s1z = s_new[5];
    }
}

extern "C" void kernel_launch(void* const* d_in, const int* in_sizes, int n_in,
                              void* d_out, int out_size) {
    (void)in_sizes; (void)n_in; (void)out_size;
    const float4* pts = (const float4*)d_in[0];
    reset_kernel<<<1, 32>>>();                    // clears lines each replay
    fps_kernel<<<CPB, TPB>>>(pts, (float*)d_out);
}

// round 15
// speedup vs baseline: 1.7160x; 1.7160x over previous
#include <cuda_runtime.h>
#include <cstdint>

// FPS: B=2, Npb=131072, stride=32 -> M=4096 samples, 4095 serial rounds.
// 64 CTAs/batch * 256 thr * 8 pts/thr (128 CTAs: single wave, spin-safe).
// R15: NO max-RMWs. Each CTA publishes one self-validating 32B packet
// (two 16B halves, each with w=(t<<17)|tail17 freshness + payload incl.
// coords) to its OWN slot with plain volatile stores, plus one relaxed
// red.add to a counter (split over two 256B-spaced lines, 32 adds each).
// warp0 polls the two counters (cheap hint, 2 broadcast loads/iter); slots
// are then read ONCE and validated per-packet by freshness word (re-read
// only if an add outran its packet -- rare). Batch argmax over the 64
// packets is done in registers; coords come from the packets, removing the
// R7 serial key->pts[idx] tail. Parity double-buffered.

#define NBATCH 2
#define CPB    64
#define TPB    256
#define PPT    8       // CPB*TPB*PPT = 131072
#define NPB    131072
#define MSAMP  4096
#define NW     (TPB / 32)
#define FLTMAX 3.402823466e38f

typedef unsigned long long u64;

struct __align__(32) Slot { uint4 a; uint4 b; };
// halfA = {dist_bits, w, x, y}   halfB = {z, w, 0, 0}
// w = (t << 17) | tail17,  tail17 = 0x1FFFF - in_batch_idx
__device__ Slot g_slot[2][NBATCH][CPB];        // [parity][batch][cta]

struct __align__(256) Cnt { unsigned v; unsigned _pad[63]; };
__device__ Cnt g_cnt[2][NBATCH][2];            // [parity][batch][half]

__global__ void reset_kernel() {
    int i = threadIdx.x;
    if (i < 2 * NBATCH * 2)
        g_cnt[i >> 2][(i >> 1) & 1][i & 1].v = 0u;
}

__device__ __forceinline__ u64 f2pack(float lo, float hi) {
    u64 r; asm("mov.b64 %0, {%1,%2};" : "=l"(r) : "f"(lo), "f"(hi)); return r;
}
__device__ __forceinline__ void f2unpack(float& lo, float& hi, u64 v) {
    asm("mov.b64 {%0,%1}, %2;" : "=f"(lo), "=f"(hi) : "l"(v));
}
__device__ __forceinline__ u64 addx2(u64 a, u64 b) {   // per-lane IEEE rn add
    u64 r; asm("add.rn.f32x2 %0, %1, %2;" : "=l"(r) : "l"(a), "l"(b)); return r;
}
__device__ __forceinline__ u64 mulx2(u64 a, u64 b) {   // per-lane IEEE rn mul
    u64 r; asm("mul.rn.f32x2 %0, %1, %2;" : "=l"(r) : "l"(a), "l"(b)); return r;
}
__device__ __forceinline__ uint4 ldv(const uint4* p) {
    uint4 v;
    asm volatile("ld.volatile.global.v4.u32 {%0,%1,%2,%3}, [%4];"
                 : "=r"(v.x), "=r"(v.y), "=r"(v.z), "=r"(v.w) : "l"(p));
    return v;
}
__device__ __forceinline__ void stv(uint4* p, uint4 v) {
    asm volatile("st.volatile.global.v4.u32 [%0], {%1,%2,%3,%4};"
                 :: "l"(p), "r"(v.x), "r"(v.y), "r"(v.z), "r"(v.w));
}
__device__ __forceinline__ void red_add_rlx(unsigned* p, unsigned v) {
    asm volatile("red.relaxed.gpu.global.add.u32 [%0], %1;" :: "l"(p), "r"(v));
}
__device__ __forceinline__ unsigned ld_rlx_u32(const unsigned* p) {
    unsigned v;
    asm volatile("ld.relaxed.gpu.global.u32 %0, [%1];" : "=r"(v) : "l"(p));
    return v;
}

__global__ void __launch_bounds__(TPB, 1)
fps_kernel(const float4* __restrict__ pts, float* __restrict__ out)
{
    const int c    = blockIdx.x;          // CTA within batch (0..63)
    const int b    = blockIdx.y;          // batch
    const int tid  = threadIdx.x;
    const int lane = tid & 31;
    const int wid  = tid >> 5;

    const int lbase = c * (TPB * PPT);    // in-batch base index of this CTA
    const int gbase = b * NPB + lbase;
    const float4* __restrict__ bpts = pts + (size_t)b * NPB;

    // Register-resident point state; coords packed 2-per-u64 for f32x2 math.
    u64 x2[PPT / 2], y2[PPT / 2], z2[PPT / 2];
    float dist[PPT];
    unsigned tail[PPT];                   // 0x1FFFF - in_batch_idx (17 bits)
#pragma unroll
    for (int i = 0; i < PPT / 2; ++i) {
        float4 v0 = pts[gbase + (2 * i) * TPB + tid];
        float4 v1 = pts[gbase + (2 * i + 1) * TPB + tid];
        x2[i] = f2pack(v0.y, v1.y);
        y2[i] = f2pack(v0.z, v1.z);
        z2[i] = f2pack(v0.w, v1.w);
        dist[2 * i] = FLTMAX; dist[2 * i + 1] = FLTMAX;
        tail[2 * i]     = 0x1FFFFu - (unsigned)(lbase + (2 * i) * TPB + tid);
        tail[2 * i + 1] = 0x1FFFFu - (unsigned)(lbase + (2 * i + 1) * TPB + tid);
    }

    // Seed sample = point 0 of the batch (pointops convention)
    float4 p0 = bpts[0];
    float sx = p0.y, sy = p0.z, sz = p0.w;
    if (c == 0 && tid == 0)
        ((float4*)out)[(size_t)b * MSAMP] = p0;

    __shared__ unsigned s_db[NW], s_tl[NW];
    __shared__ float    s_x[NW], s_y[NW], s_z[NW];
    __shared__ float    s_new[3];

    for (int t = 1; t < MSAMP; ++t) {
        const unsigned tgt = (unsigned)t;
        // negate once (exact); x + (-s) is bit-identical to x - s in rn
        u64 nsx = f2pack(-sx, -sx);
        u64 nsy = f2pack(-sy, -sy);
        u64 nsz = f2pack(-sz, -sz);

        // ---- local dist update + per-thread argmax (bit compare == float
        // compare for non-negative f32; strict > keeps lowest idx since idx
        // ascends within the thread -> matches jnp.argmax first-max) ----
        unsigned bdb = 0u, btl = 0u;
        float bx = 0.f, by = 0.f, bz = 0.f;
#pragma unroll
        for (int i = 0; i < PPT / 2; ++i) {
            u64 dx = addx2(x2[i], nsx);
            u64 dy = addx2(y2[i], nsy);
            u64 dz = addx2(z2[i], nsz);
            // unfused, left-to-right (dx*dx + dy*dy) + dz*dz == reference
            u64 s = addx2(addx2(mulx2(dx, dx), mulx2(dy, dy)), mulx2(dz, dz));
            float d0, d1; f2unpack(d0, d1, s);
            float nd0 = fminf(dist[2 * i], d0);
            float nd1 = fminf(dist[2 * i + 1], d1);
            dist[2 * i] = nd0; dist[2 * i + 1] = nd1;
            unsigned db0 = __float_as_uint(nd0);
            unsigned db1 = __float_as_uint(nd1);
            float px0, px1, py0, py1, pz0, pz1;
            f2unpack(px0, px1, x2[i]);
            f2unpack(py0, py1, y2[i]);
            f2unpack(pz0, pz1, z2[i]);
            if (db0 > bdb) { bdb = db0; btl = tail[2 * i];
                             bx = px0; by = py0; bz = pz0; }
            if (db1 > bdb) { bdb = db1; btl = tail[2 * i + 1];
                             bx = px1; by = py1; bz = pz1; }
        }

        // ---- warp argmax: max dist-bits, tie -> max tail (= lowest idx) ----
        unsigned m  = __reduce_max_sync(0xFFFFFFFFu, bdb);
        unsigned mt = __reduce_max_sync(0xFFFFFFFFu, (bdb == m) ? btl : 0u);
        if (bdb == m && btl == mt) {      // unique winning lane
            s_db[wid] = m; s_tl[wid] = mt;
            s_x[wid] = bx; s_y[wid] = by; s_z[wid] = bz;
        }
        __syncthreads();

        if (wid == 0) {
            // ---- block argmax over NW warp winners ----
            unsigned db2 = (lane < NW) ? s_db[lane] : 0u;
            unsigned tl2 = (lane < NW) ? s_tl[lane] : 0u;
            unsigned m2  = __reduce_max_sync(0xFFFFFFFFu, db2);
            unsigned mt2 = __reduce_max_sync(0xFFFFFFFFu, (db2 == m2) ? tl2 : 0u);

            // ---- publish: winning lane stores the packet (plain volatile
            // stores, NO RMW), then bumps its counter half (relaxed add;
            // per-packet freshness validation replaces release ordering) ----
            if (db2 == m2 && tl2 == mt2) {
                unsigned w = (tgt << 17) | mt2;
                Slot* sp = &g_slot[t & 1][b][c];
                stv(&sp->b, make_uint4(__float_as_uint(s_z[lane]), w, 0u, 0u));
                stv(&sp->a, make_uint4(m2, w, __float_as_uint(s_x[lane]),
                                       __float_as_uint(s_y[lane])));
                red_add_rlx(&g_cnt[t & 1][b][c >> 5].v, 1u);
            }

            // ---- detect hint: poll the two 4B counters (separate 256B
            // lines -> separate slices; 2 broadcast loads/iter). '>=' safe:
            // this parity passes target only after all CTAs consumed t. ----
            const unsigned tg32 = 32u * (unsigned)((t + 1) >> 1);
            unsigned c0, c1;
            do {
                c0 = ld_rlx_u32(&g_cnt[t & 1][b][0].v);
                c1 = ld_rlx_u32(&g_cnt[t & 1][b][1].v);
            } while (c0 < tg32 || c1 < tg32);

            // ---- consume: read 64 slots (2/lane), validate freshness;
            // re-read only if a relaxed add outran its packet (rare) ----
            Slot* s0 = &g_slot[t & 1][b][lane];
            Slot* s1 = &g_slot[t & 1][b][lane + 32];
            uint4 A0, B0, A1, B1;
            do {
                A0 = ldv(&s0->a); B0 = ldv(&s0->b);
                A1 = ldv(&s1->a); B1 = ldv(&s1->b);
            } while ((A0.y >> 17) != tgt || (B0.y >> 17) != tgt ||
                     (A1.y >> 17) != tgt || (B1.y >> 17) != tgt);

            // fold the lane's two candidates (same t prefix: compare w raw)
            unsigned db3 = A0.x, w3 = A0.y;
            float fx = __uint_as_float(A0.z), fy = __uint_as_float(A0.w);
            float fz = __uint_as_float(B0.x);
            if (A1.x > db3 || (A1.x == db3 && A1.y > w3)) {
                db3 = A1.x; w3 = A1.y;
                fx = __uint_as_float(A1.z); fy = __uint_as_float(A1.w);
                fz = __uint_as_float(B1.x);
            }

            // ---- batch argmax over the folded candidates ----
            unsigned m3 = __reduce_max_sync(0xFFFFFFFFu, db3);
            unsigned mw = __reduce_max_sync(0xFFFFFFFFu, (db3 == m3) ? w3 : 0u);
            int win = (db3 == m3 && w3 == mw);
            unsigned wl = 31 - __clz(__ballot_sync(0xFFFFFFFFu, win));
            float wx = __shfl_sync(0xFFFFFFFFu, fx, wl);
            float wy = __shfl_sync(0xFFFFFFFFu, fy, wl);
            float wz = __shfl_sync(0xFFFFFFFFu, fz, wl);

            if (lane == 0) {
                s_new[0] = wx; s_new[1] = wy; s_new[2] = wz;
                if (c == 0) {
                    float* o = out + ((size_t)b * MSAMP + t) * 4;
                    o[0] = (float)b; o[1] = wx; o[2] = wy; o[3] = wz;
                }
            }
        }
        __syncthreads();
        sx = s_new[0]; sy = s_new[1]; sz = s_new[2];
    }
}

extern "C" void kernel_launch(void* const* d_in, const int* in_sizes, int n_in,
                              void* d_out, int out_size) {
    (void)in_sizes; (void)n_in; (void)out_size;
    const float4* pts = (const float4*)d_in[0];
    reset_kernel<<<1, 32>>>();                    // clears counters each replay
    dim3 grid(CPB, NBATCH);
    fps_kernel<<<grid, TPB>>>(pts, (float*)d_out);
}